// round 7
// baseline (speedup 1.0000x reference)
#include <cuda_runtime.h>
#include <cuda_fp16.h>
#include <math.h>
#include <stdint.h>

#define N_OBJ   128
#define HW      36864      // 192*192
#define CLSD    128
#define POSD    64
#define NCLS    80
#define TP      128        // pixels per block tile (main)
#define GRIDM   (HW / TP)  // 288 blocks; occ 2/SM -> 296 slots -> 1 wave
#define ROWA    272        // fp16 row stride bytes (17 x 16B -> LDSM conflict-free)
#define ROWB    272
#define A_BYTES (128 * ROWA)   // 34816
#define B_BYTES (128 * ROWB)   // 34816

// -------- scratch (__device__ globals) --------------------------------------
__device__ float  g_T[NCLS * NCLS];        // class table T[a][b]
__device__ __half g_rel[N_OBJ * N_OBJ];    // relation_score fp16, [n][m]

__device__ __forceinline__ float fsig(float x) {   // sigmoid via single MUFU
    float t;
    asm("tanh.approx.f32 %0, %1;" : "=f"(t) : "f"(0.5f * x));
    return fmaf(0.5f, t, 0.5f);
}
__device__ __forceinline__ uint32_t smem_u32(const void* p) {
    uint32_t a;
    asm("{ .reg .u64 t; cvta.to.shared.u64 t, %1; cvt.u32.u64 %0, t; }" : "=r"(a) : "l"(p));
    return a;
}
__device__ __forceinline__ void ldmx4(uint32_t r[4], uint32_t addr) {
    asm volatile("ldmatrix.sync.aligned.m8n8.x4.shared.b16 {%0,%1,%2,%3}, [%4];"
        : "=r"(r[0]), "=r"(r[1]), "=r"(r[2]), "=r"(r[3]) : "r"(addr));
}
__device__ __forceinline__ void ldmx2t(uint32_t r[2], uint32_t addr) {
    asm volatile("ldmatrix.sync.aligned.m8n8.x2.trans.shared.b16 {%0,%1}, [%2];"
        : "=r"(r[0]), "=r"(r[1]) : "r"(addr));
}
__device__ __forceinline__ void mma_fp16(float c[4], const uint32_t a[4], const uint32_t b[2]) {
    asm volatile(
        "mma.sync.aligned.m16n8k16.row.col.f32.f16.f16.f32 "
        "{%0,%1,%2,%3}, {%4,%5,%6,%7}, {%8,%9}, {%0,%1,%2,%3};"
        : "+f"(c[0]), "+f"(c[1]), "+f"(c[2]), "+f"(c[3])
        : "r"(a[0]), "r"(a[1]), "r"(a[2]), "r"(a[3]), "r"(b[0]), "r"(b[1]));
}

// ============================================================================
// Kernel 1: class table T[a][b] = sum_k relu(W_U[a,k])*W_P[k]*relu(W_V[b,k])
// ONE WARP PER (a,b) PAIR: 800 blocks x 8 warps = 6400 warps, fully parallel.
// Per warp: 2 coalesced float4 loads/lane + 16 FMA + shuffle reduce + 1 STG.
// ============================================================================
__global__ void __launch_bounds__(256)
ttab_kernel(const float* __restrict__ W_U,
            const float* __restrict__ W_V,
            const float* __restrict__ W_P)
{
    const int tid  = threadIdx.x;
    const int wid  = tid >> 5;
    const int lane = tid & 31;
    const int pair = blockIdx.x * 8 + wid;     // 0..6399
    const int a = pair / NCLS;
    const int b = pair - a * NCLS;

    const float4 u4 = *(const float4*)&W_U[a * CLSD + lane * 4];
    const float4 v4 = *(const float4*)&W_V[b * CLSD + lane * 4];
    const float4 p4 = *(const float4*)&W_P[lane * 4];

    float acc = fmaxf(u4.x, 0.0f) * p4.x * fmaxf(v4.x, 0.0f)
              + fmaxf(u4.y, 0.0f) * p4.y * fmaxf(v4.y, 0.0f)
              + fmaxf(u4.z, 0.0f) * p4.z * fmaxf(v4.z, 0.0f)
              + fmaxf(u4.w, 0.0f) * p4.w * fmaxf(v4.w, 0.0f);

#pragma unroll
    for (int o = 16; o > 0; o >>= 1)
        acc += __shfl_xor_sync(0xFFFFFFFFu, acc, o);

    if (lane == 0) g_T[a * NCLS + b] = acc;
}

// ============================================================================
// Kernel 2: fused score+rel. Thread (n,m) computes S[n,m] AND S[m,n] directly
// (T lookups + both-direction pos terms), writes rel[n,m]=relu(S_nm-S_mn) fp16.
// grid 128 (n), block 128 (m).
// ============================================================================
__global__ void __launch_bounds__(128)
score_rel_kernel(const float* __restrict__ bbox,
                 const float* __restrict__ W_pos,
                 const float* __restrict__ W_P,
                 const int*   __restrict__ cls_idx)
{
    const int n = blockIdx.x;
    const int m = threadIdx.x;

    __shared__ float wpos_s[4][POSD];
    __shared__ float wp2[POSD];
    __shared__ int   scls[N_OBJ];

    scls[m] = cls_idx[m] - 1;
    if (m < POSD) {
        wp2[m] = W_P[CLSD + m];
        wpos_s[0][m] = W_pos[0 * POSD + m];
        wpos_s[1][m] = W_pos[1 * POSD + m];
        wpos_s[2][m] = W_pos[2 * POSD + m];
        wpos_s[3][m] = W_pos[3 * POSD + m];
    }
    __syncthreads();

    const float4 bn = *(const float4*)&bbox[n * 4];   // broadcast (same line)
    const float4 bm = *(const float4*)&bbox[m * 4];   // coalesced
    const float wn = bn.z - bn.x, hn = bn.w - bn.y;
    const float wm = bm.z - bm.x, hm = bm.w - bm.y;
    const float xcn = 0.5f * (bn.x + bn.z), ycn = 0.5f * (bn.y + bn.w);
    const float xcm = 0.5f * (bm.x + bm.z), ycm = 0.5f * (bm.y + bm.w);

    const float dx1 = __fdividef(xcm - xcn, wn);      // (n,m) direction
    const float dy1 = __fdividef(ycm - ycn, hn);
    const float dw1 = __logf(__fdividef(wm, wn));
    const float dh1 = __logf(__fdividef(hm, hn));
    const float dx2 = __fdividef(xcn - xcm, wm);      // (m,n) direction
    const float dy2 = __fdividef(ycn - ycm, hm);
    const float dw2 = -dw1;
    const float dh2 = -dh1;

    float p1 = 0.0f, p2 = 0.0f;
#pragma unroll 8
    for (int d = 0; d < POSD; d++) {
        const float w0 = wpos_s[0][d], w1 = wpos_s[1][d],
                    w2 = wpos_s[2][d], w3 = wpos_s[3][d], wp = wp2[d];
        float t1 = dx1 * w0 + dy1 * w1 + dw1 * w2 + dh1 * w3;
        float t2 = dx2 * w0 + dy2 * w1 + dw2 * w2 + dh2 * w3;
        p1 += fmaxf(t1, 0.0f) * wp;
        p2 += fmaxf(t2, 0.0f) * wp;
    }

    const int cn = scls[n], cm = scls[m];
    const float Tnm = g_T[cn * NCLS + cm];
    const float Tmn = g_T[cm * NCLS + cn];

    const float r = fmaxf(fsig(Tnm + p1) - fsig(Tmn + p2), 0.0f);
    g_rel[n * N_OBJ + m] = __float2half_rn(r);
}

// ============================================================================
// Kernel 3: main GEMM. 128-pixel tile, fp16 mma.sync, 2 CTAs/SM.
// smem: A = rel [n][m] fp16 (128 x 272B), B = sigmoid(L) [m][p] fp16 (128 x 272B)
// ============================================================================
__global__ void __launch_bounds__(256, 2)
main_kernel(const float* __restrict__ L, float* __restrict__ out)
{
    extern __shared__ __align__(128) char sm[];
    char* smA = sm;
    char* smB = sm + A_BYTES;

    const int tid  = threadIdx.x;
    const int wid  = tid >> 5;
    const int lane = tid & 31;
    const int P    = blockIdx.x * TP;

    // ---- stage A (rel fp16): contiguous u32 copies -------------------------
    {
        const uint32_t* __restrict__ rr = (const uint32_t*)g_rel;
#pragma unroll
        for (int e = 0; e < 8192 / 256; e++) {
            int idx = tid + e * 256;
            int nn = idx >> 6, mp = idx & 63;
            *(uint32_t*)(smA + nn * ROWA + mp * 4) = rr[idx];
        }
    }
    // ---- stage B: sigmoid(L) -> fp16, natural [m][p] ------------------------
#pragma unroll
    for (int e = 0; e < 8192 / 256; e++) {
        int idx = tid + e * 256;          // half2 index
        int mm = idx >> 6, pp = idx & 63;
        float2 l2 = *(const float2*)&L[(size_t)mm * HW + P + pp * 2];
        *(__half2*)(smB + mm * ROWB + pp * 4) = __floats2half2_rn(fsig(l2.x), fsig(l2.y));
    }
    __syncthreads();

    // ---- warp tiling: 2 n-groups x 4 p-groups; warp = n64 x p32 ------------
    const int nb = (wid >> 2) * 64;
    const int pb = (wid & 3) * 32;

    float acc[4][4][4];
#pragma unroll
    for (int a = 0; a < 4; a++)
#pragma unroll
        for (int b = 0; b < 4; b++)
#pragma unroll
            for (int q = 0; q < 4; q++) acc[a][b][q] = 0.0f;

    const int a_grp = lane >> 3;
    const int a_row = (a_grp & 1) * 8 + (lane & 7);
    const int a_col = (a_grp >> 1) * 8;
    const int b_row = lane & 15;

    const uint32_t uA = smem_u32(smA);
    const uint32_t uB = smem_u32(smB);

#pragma unroll
    for (int kc = 0; kc < 8; kc++) {
        const int k0 = kc * 16;
        uint32_t Af[4][4];
#pragma unroll
        for (int a = 0; a < 4; a++)
            ldmx4(Af[a], uA + (uint32_t)((nb + a * 16 + a_row) * ROWA + (k0 + a_col) * 2));
        uint32_t Bf[4][2];
#pragma unroll
        for (int b = 0; b < 4; b++)
            ldmx2t(Bf[b], uB + (uint32_t)((k0 + b_row) * ROWB + (pb + b * 8) * 2));
#pragma unroll
        for (int a = 0; a < 4; a++)
#pragma unroll
            for (int b = 0; b < 4; b++)
                mma_fp16(acc[a][b], Af[a], Bf[b]);
    }

    // ---- epilogue: out = L * (1 - sigmoid(L) * w) ---------------------------
    const int g = lane >> 2, t4 = lane & 3;
#pragma unroll
    for (int a = 0; a < 4; a++) {
#pragma unroll
        for (int b = 0; b < 4; b++) {
            const int n0 = nb + a * 16 + g;
            const int p0 = P + pb + b * 8 + 2 * t4;
            {
                size_t off = (size_t)n0 * HW + p0;
                float2 lv = *(const float2*)&L[off];
                float2 ov;
                ov.x = lv.x * (1.0f - fsig(lv.x) * acc[a][b][0]);
                ov.y = lv.y * (1.0f - fsig(lv.y) * acc[a][b][1]);
                *(float2*)&out[off] = ov;
            }
            {
                size_t off = (size_t)(n0 + 8) * HW + p0;
                float2 lv = *(const float2*)&L[off];
                float2 ov;
                ov.x = lv.x * (1.0f - fsig(lv.x) * acc[a][b][2]);
                ov.y = lv.y * (1.0f - fsig(lv.y) * acc[a][b][3]);
                *(float2*)&out[off] = ov;
            }
        }
    }
}

// ============================================================================
extern "C" void kernel_launch(void* const* d_in, const int* in_sizes, int n_in,
                              void* d_out, int out_size)
{
    const float* L     = (const float*)d_in[0];   // mask_logits (1,128,192,192)
    const float* bbox  = (const float*)d_in[1];   // (128,4)
    const float* W_U   = (const float*)d_in[2];   // (80,128)
    const float* W_V   = (const float*)d_in[3];   // (80,128)
    const float* W_pos = (const float*)d_in[4];   // (4,64)
    const float* W_P   = (const float*)d_in[5];   // (192,1)
    const int*   cls   = (const int*)d_in[6];     // (128,)
    float* out = (float*)d_out;

    const int dyn_smem = A_BYTES + B_BYTES;       // 69632 B -> 2 CTAs/SM
    cudaFuncSetAttribute(main_kernel,
                         cudaFuncAttributeMaxDynamicSharedMemorySize, dyn_smem);

    ttab_kernel<<<(NCLS * NCLS) / 8, 256>>>(W_U, W_V, W_P);
    score_rel_kernel<<<N_OBJ, N_OBJ>>>(bbox, W_pos, W_P, cls);
    main_kernel<<<GRIDM, 256, dyn_smem>>>(L, out);
}

// round 8
// speedup vs baseline: 1.0152x; 1.0152x over previous
#include <cuda_runtime.h>
#include <cuda_fp16.h>
#include <math.h>
#include <stdint.h>

#define N_OBJ   128
#define HW      36864      // 192*192
#define CLSD    128
#define POSD    64
#define NCLS    80
#define TP      128        // pixels per block tile (main)
#define GRIDM   (HW / TP)  // 288 blocks; occ 2/SM -> 296 slots -> 1 wave
#define ROWA    272        // fp16 row stride bytes (17 x 16B -> LDSM conflict-free)
#define ROWB    272
#define A_BYTES (128 * ROWA)   // 34816
#define B_BYTES (128 * ROWB)   // 34816

// -------- scratch (__device__ globals) --------------------------------------
__device__ __half g_rel[N_OBJ * N_OBJ];    // relation_score fp16, [n][m]

__device__ __forceinline__ float fsig(float x) {   // sigmoid via single MUFU
    float t;
    asm("tanh.approx.f32 %0, %1;" : "=f"(t) : "f"(0.5f * x));
    return fmaf(0.5f, t, 0.5f);
}
__device__ __forceinline__ uint32_t smem_u32(const void* p) {
    uint32_t a;
    asm("{ .reg .u64 t; cvta.to.shared.u64 t, %1; cvt.u32.u64 %0, t; }" : "=r"(a) : "l"(p));
    return a;
}
__device__ __forceinline__ void ldmx4(uint32_t r[4], uint32_t addr) {
    asm volatile("ldmatrix.sync.aligned.m8n8.x4.shared.b16 {%0,%1,%2,%3}, [%4];"
        : "=r"(r[0]), "=r"(r[1]), "=r"(r[2]), "=r"(r[3]) : "r"(addr));
}
__device__ __forceinline__ void ldmx2t(uint32_t r[2], uint32_t addr) {
    asm volatile("ldmatrix.sync.aligned.m8n8.x2.trans.shared.b16 {%0,%1}, [%2];"
        : "=r"(r[0]), "=r"(r[1]) : "r"(addr));
}
__device__ __forceinline__ void mma_fp16(float c[4], const uint32_t a[4], const uint32_t b[2]) {
    asm volatile(
        "mma.sync.aligned.m16n8k16.row.col.f32.f16.f16.f32 "
        "{%0,%1,%2,%3}, {%4,%5,%6,%7}, {%8,%9}, {%0,%1,%2,%3};"
        : "+f"(c[0]), "+f"(c[1]), "+f"(c[2]), "+f"(c[3])
        : "r"(a[0]), "r"(a[1]), "r"(a[2]), "r"(a[3]), "r"(b[0]), "r"(b[1]));
}

// ============================================================================
// Kernel 1 (fused ttab + score + rel). Block n, 128 threads (m).
// Phase 0: stage uP[k]=relu(W_U[cn,k])*WP[k], pv[k]=WP[k]*relu(W_V[cn,k]).
// Phase 1: 4 warps compute Trow[c]=T[cn][c], Tcol[c]=T[c][cn] for 80 classes.
// Phase 2: thread m computes S[n,m], S[m,n] and writes rel fp16.
// ============================================================================
__global__ void __launch_bounds__(128)
score_rel_kernel(const float* __restrict__ bbox,
                 const float* __restrict__ W_U,
                 const float* __restrict__ W_V,
                 const float* __restrict__ W_pos,
                 const float* __restrict__ W_P,
                 const int*   __restrict__ cls_idx)
{
    const int n    = blockIdx.x;
    const int m    = threadIdx.x;
    const int wid  = m >> 5;
    const int lane = m & 31;

    __shared__ __align__(16) float uP[CLSD];    // relu(W_U[cn,k]) * WP[k]
    __shared__ __align__(16) float pv[CLSD];    // WP[k] * relu(W_V[cn,k])
    __shared__ float Trow[NCLS];                // T[cn][c]
    __shared__ float Tcol[NCLS];                // T[c][cn]
    __shared__ float wpos_s[4][POSD];
    __shared__ float wp2[POSD];
    __shared__ int   scls[N_OBJ];

    const int cn = cls_idx[n] - 1;

    // ---- phase 0: stage per-block vectors ----------------------------------
    {
        const float wpk = W_P[m];
        uP[m] = fmaxf(W_U[cn * CLSD + m], 0.0f) * wpk;
        pv[m] = wpk * fmaxf(W_V[cn * CLSD + m], 0.0f);
        scls[m] = cls_idx[m] - 1;
        if (m < POSD) {
            wp2[m] = W_P[CLSD + m];
            wpos_s[0][m] = W_pos[0 * POSD + m];
            wpos_s[1][m] = W_pos[1 * POSD + m];
            wpos_s[2][m] = W_pos[2 * POSD + m];
            wpos_s[3][m] = W_pos[3 * POSD + m];
        }
    }
    __syncthreads();

    // ---- phase 1: Trow / Tcol (4 warps x 20 classes) ------------------------
    {
        const float4 u4 = *(const float4*)&uP[lane * 4];
        const float4 p4 = *(const float4*)&pv[lane * 4];
#pragma unroll
        for (int it = 0; it < NCLS / 4; it++) {
            const int c = wid * (NCLS / 4) + it;
            float4 v = *(const float4*)&W_V[c * CLSD + lane * 4];   // L2-hot
            float4 u = *(const float4*)&W_U[c * CLSD + lane * 4];
            float a1 = fmaxf(v.x, 0.0f) * u4.x + fmaxf(v.y, 0.0f) * u4.y
                     + fmaxf(v.z, 0.0f) * u4.z + fmaxf(v.w, 0.0f) * u4.w;
            float a2 = fmaxf(u.x, 0.0f) * p4.x + fmaxf(u.y, 0.0f) * p4.y
                     + fmaxf(u.z, 0.0f) * p4.z + fmaxf(u.w, 0.0f) * p4.w;
#pragma unroll
            for (int o = 16; o > 0; o >>= 1) {
                a1 += __shfl_xor_sync(0xFFFFFFFFu, a1, o);
                a2 += __shfl_xor_sync(0xFFFFFFFFu, a2, o);
            }
            if (lane == 0) { Trow[c] = a1; Tcol[c] = a2; }
        }
    }
    __syncthreads();

    // ---- phase 2: score both directions + rel -------------------------------
    const float4 bn = *(const float4*)&bbox[n * 4];   // broadcast
    const float4 bm = *(const float4*)&bbox[m * 4];   // coalesced
    const float wn = bn.z - bn.x, hn = bn.w - bn.y;
    const float wm = bm.z - bm.x, hm = bm.w - bm.y;
    const float xcn = 0.5f * (bn.x + bn.z), ycn = 0.5f * (bn.y + bn.w);
    const float xcm = 0.5f * (bm.x + bm.z), ycm = 0.5f * (bm.y + bm.w);

    const float dx1 = __fdividef(xcm - xcn, wn);      // (n,m) direction
    const float dy1 = __fdividef(ycm - ycn, hn);
    const float dw1 = __logf(__fdividef(wm, wn));
    const float dh1 = __logf(__fdividef(hm, hn));
    const float dx2 = __fdividef(xcn - xcm, wm);      // (m,n) direction
    const float dy2 = __fdividef(ycn - ycm, hm);
    const float dw2 = -dw1;
    const float dh2 = -dh1;

    float p1 = 0.0f, p2 = 0.0f;
#pragma unroll 8
    for (int d = 0; d < POSD; d++) {
        const float w0 = wpos_s[0][d], w1 = wpos_s[1][d],
                    w2 = wpos_s[2][d], w3 = wpos_s[3][d], wp = wp2[d];
        float t1 = dx1 * w0 + dy1 * w1 + dw1 * w2 + dh1 * w3;
        float t2 = dx2 * w0 + dy2 * w1 + dw2 * w2 + dh2 * w3;
        p1 += fmaxf(t1, 0.0f) * wp;
        p2 += fmaxf(t2, 0.0f) * wp;
    }

    const int cm = scls[m];
    const float r = fmaxf(fsig(Trow[cm] + p1) - fsig(Tcol[cm] + p2), 0.0f);
    g_rel[n * N_OBJ + m] = __float2half_rn(r);
}

// ============================================================================
// Kernel 2: main GEMM. 128-pixel tile, fp16 mma.sync, 2 CTAs/SM.
// smem: A = rel [n][m] fp16 (128 x 272B), B = sigmoid(L) [m][p] fp16 (128 x 272B)
// ============================================================================
__global__ void __launch_bounds__(256, 2)
main_kernel(const float* __restrict__ L, float* __restrict__ out)
{
    extern __shared__ __align__(128) char sm[];
    char* smA = sm;
    char* smB = sm + A_BYTES;

    const int tid  = threadIdx.x;
    const int wid  = tid >> 5;
    const int lane = tid & 31;
    const int P    = blockIdx.x * TP;

    // ---- stage A (rel fp16): contiguous u32 copies -------------------------
    {
        const uint32_t* __restrict__ rr = (const uint32_t*)g_rel;
#pragma unroll
        for (int e = 0; e < 8192 / 256; e++) {
            int idx = tid + e * 256;
            int nn = idx >> 6, mp = idx & 63;
            *(uint32_t*)(smA + nn * ROWA + mp * 4) = rr[idx];
        }
    }
    // ---- stage B: sigmoid(L) -> fp16, natural [m][p] ------------------------
#pragma unroll
    for (int e = 0; e < 8192 / 256; e++) {
        int idx = tid + e * 256;          // half2 index
        int mm = idx >> 6, pp = idx & 63;
        float2 l2 = *(const float2*)&L[(size_t)mm * HW + P + pp * 2];
        *(__half2*)(smB + mm * ROWB + pp * 4) = __floats2half2_rn(fsig(l2.x), fsig(l2.y));
    }
    __syncthreads();

    // ---- warp tiling: 2 n-groups x 4 p-groups; warp = n64 x p32 ------------
    const int nb = (wid >> 2) * 64;
    const int pb = (wid & 3) * 32;

    float acc[4][4][4];
#pragma unroll
    for (int a = 0; a < 4; a++)
#pragma unroll
        for (int b = 0; b < 4; b++)
#pragma unroll
            for (int q = 0; q < 4; q++) acc[a][b][q] = 0.0f;

    const int a_grp = lane >> 3;
    const int a_row = (a_grp & 1) * 8 + (lane & 7);
    const int a_col = (a_grp >> 1) * 8;
    const int b_row = lane & 15;

    const uint32_t uA = smem_u32(smA);
    const uint32_t uB = smem_u32(smB);

#pragma unroll
    for (int kc = 0; kc < 8; kc++) {
        const int k0 = kc * 16;
        uint32_t Af[4][4];
#pragma unroll
        for (int a = 0; a < 4; a++)
            ldmx4(Af[a], uA + (uint32_t)((nb + a * 16 + a_row) * ROWA + (k0 + a_col) * 2));
        uint32_t Bf[4][2];
#pragma unroll
        for (int b = 0; b < 4; b++)
            ldmx2t(Bf[b], uB + (uint32_t)((k0 + b_row) * ROWB + (pb + b * 8) * 2));
#pragma unroll
        for (int a = 0; a < 4; a++)
#pragma unroll
            for (int b = 0; b < 4; b++)
                mma_fp16(acc[a][b], Af[a], Bf[b]);
    }

    // ---- epilogue: out = L * (1 - sigmoid(L) * w) ---------------------------
    const int g = lane >> 2, t4 = lane & 3;
#pragma unroll
    for (int a = 0; a < 4; a++) {
#pragma unroll
        for (int b = 0; b < 4; b++) {
            const int n0 = nb + a * 16 + g;
            const int p0 = P + pb + b * 8 + 2 * t4;
            {
                size_t off = (size_t)n0 * HW + p0;
                float2 lv = *(const float2*)&L[off];
                float2 ov;
                ov.x = lv.x * (1.0f - fsig(lv.x) * acc[a][b][0]);
                ov.y = lv.y * (1.0f - fsig(lv.y) * acc[a][b][1]);
                *(float2*)&out[off] = ov;
            }
            {
                size_t off = (size_t)(n0 + 8) * HW + p0;
                float2 lv = *(const float2*)&L[off];
                float2 ov;
                ov.x = lv.x * (1.0f - fsig(lv.x) * acc[a][b][2]);
                ov.y = lv.y * (1.0f - fsig(lv.y) * acc[a][b][3]);
                *(float2*)&out[off] = ov;
            }
        }
    }
}

// ============================================================================
extern "C" void kernel_launch(void* const* d_in, const int* in_sizes, int n_in,
                              void* d_out, int out_size)
{
    const float* L     = (const float*)d_in[0];   // mask_logits (1,128,192,192)
    const float* bbox  = (const float*)d_in[1];   // (128,4)
    const float* W_U   = (const float*)d_in[2];   // (80,128)
    const float* W_V   = (const float*)d_in[3];   // (80,128)
    const float* W_pos = (const float*)d_in[4];   // (4,64)
    const float* W_P   = (const float*)d_in[5];   // (192,1)
    const int*   cls   = (const int*)d_in[6];     // (128,)
    float* out = (float*)d_out;

    const int dyn_smem = A_BYTES + B_BYTES;       // 69632 B -> 2 CTAs/SM
    cudaFuncSetAttribute(main_kernel,
                         cudaFuncAttributeMaxDynamicSharedMemorySize, dyn_smem);

    score_rel_kernel<<<N_OBJ, N_OBJ>>>(bbox, W_U, W_V, W_pos, W_P, cls);
    main_kernel<<<GRIDM, 256, dyn_smem>>>(L, out);
}